// round 2
// baseline (speedup 1.0000x reference)
#include <cuda_runtime.h>

// AttributeBiasLoss — exact emulation of the reference's fp32 arithmetic.
//
// Key insight: the reference (jax on CPU) computes segment_sum as a SEQUENTIAL
// fp32 scatter-add in row order. Its bin sums carry ~0.4 absolute random-walk
// rounding error (bin mean err ~3.5e-6), which dominates the 1e-3 rel-err
// budget of this cancellation-heavy loss. We must reproduce the same fold:
//   K1: per_node[b] = fp32(mean of 8 sigmoids), left-to-right fp32 adds
//   K2: stable partition of per_node into 128 (attr,value) bins, row order
//   K3: per-bin sequential fp32 left-fold (exactly scatter-add semantics)
//   K4: fp32 means, fp32 diffs/squares, final reduction.

#define MAX_B     2097152
#define CHUNK     2048
#define MAX_NCHUNK (MAX_B / CHUNK)
#define NBIN      128
#define FOLD_BUF  2048   // floats per double-buffer half

__device__ float    g_pernode[MAX_B];
__device__ float    g_sorted[MAX_B * 8];
__device__ unsigned g_counts[MAX_NCHUNK * NBIN];
__device__ unsigned g_chunkoff[MAX_NCHUNK * NBIN];
__device__ unsigned g_bintotal[NBIN];
__device__ unsigned g_binbase[NBIN];
__device__ float    g_binmean[NBIN];

__device__ __forceinline__ float ref_sigmoid(float x) {
    float e = expf(-x);
    return __fdiv_rn(1.0f, __fadd_rn(1.0f, e));
}

// ---------------- K1: per-node mean of sigmoids (pinned fp32 order) --------
__global__ void __launch_bounds__(256) k1_pernode(const float* __restrict__ pred, int B) {
    int b = blockIdx.x * blockDim.x + threadIdx.x;
    if (b >= B) return;
    const float4* p = reinterpret_cast<const float4*>(pred + (size_t)b * 8);
    float4 p0 = __ldg(p), p1 = __ldg(p + 1);
    float s = ref_sigmoid(p0.x);
    s = __fadd_rn(s, ref_sigmoid(p0.y));
    s = __fadd_rn(s, ref_sigmoid(p0.z));
    s = __fadd_rn(s, ref_sigmoid(p0.w));
    s = __fadd_rn(s, ref_sigmoid(p1.x));
    s = __fadd_rn(s, ref_sigmoid(p1.y));
    s = __fadd_rn(s, ref_sigmoid(p1.z));
    s = __fadd_rn(s, ref_sigmoid(p1.w));
    g_pernode[b] = __fmul_rn(s, 0.125f);   // *1/8 exact
}

// ---------------- K2a: per-chunk bin counts --------------------------------
__global__ void __launch_bounds__(256) k2a_count(const int* __restrict__ attrs, int B) {
    __shared__ unsigned cnt[NBIN];
    for (int i = threadIdx.x; i < NBIN; i += blockDim.x) cnt[i] = 0;
    __syncthreads();
    int start = blockIdx.x * CHUNK;
    int end   = min(start + CHUNK, B);
    for (int r = start + threadIdx.x; r < end; r += blockDim.x) {
        const int4* a = reinterpret_cast<const int4*>(attrs + (size_t)r * 8);
        int4 a0 = __ldg(a), a1 = __ldg(a + 1);
        atomicAdd(&cnt[  0 + a0.x], 1u);
        atomicAdd(&cnt[ 16 + a0.y], 1u);
        atomicAdd(&cnt[ 32 + a0.z], 1u);
        atomicAdd(&cnt[ 48 + a0.w], 1u);
        atomicAdd(&cnt[ 64 + a1.x], 1u);
        atomicAdd(&cnt[ 80 + a1.y], 1u);
        atomicAdd(&cnt[ 96 + a1.z], 1u);
        atomicAdd(&cnt[112 + a1.w], 1u);
    }
    __syncthreads();
    for (int i = threadIdx.x; i < NBIN; i += blockDim.x)
        g_counts[blockIdx.x * NBIN + i] = cnt[i];
}

// ---------------- K2b: per-bin scan over chunks + bin bases ----------------
__global__ void __launch_bounds__(128) k2b_scan(int nchunk) {
    int t = threadIdx.x;          // bin id
    unsigned run = 0;
    for (int c = 0; c < nchunk; c++) {
        g_chunkoff[c * NBIN + t] = run;
        run += g_counts[c * NBIN + t];
    }
    g_bintotal[t] = run;
    __shared__ unsigned tot[NBIN];
    __shared__ unsigned base[NBIN];
    tot[t] = run;
    __syncthreads();
    if (t == 0) {
        unsigned acc = 0;
        for (int i = 0; i < NBIN; i++) { base[i] = acc; acc += tot[i]; }
    }
    __syncthreads();
    g_binbase[t] = base[t];
}

// ---------------- K2c: stable scatter (row order preserved per bin) --------
__global__ void __launch_bounds__(32) k2c_scatter(const int* __restrict__ attrs, int B) {
    __shared__ unsigned soff[NBIN];
    int lane  = threadIdx.x;
    int chunk = blockIdx.x;
    for (int i = lane; i < NBIN; i += 32)
        soff[i] = g_binbase[i] + g_chunkoff[chunk * NBIN + i];
    __syncwarp();
    int start = chunk * CHUNK;
    #pragma unroll 1
    for (int s = 0; s < CHUNK / 32; s++) {
        int  r   = start + s * 32 + lane;
        bool act = (r < B);
        float pn = 0.f;
        int v[8];
        if (act) {
            const int4* ap = reinterpret_cast<const int4*>(attrs + (size_t)r * 8);
            int4 a0 = __ldg(ap), a1 = __ldg(ap + 1);
            v[0] = a0.x; v[1] = a0.y; v[2] = a0.z; v[3] = a0.w;
            v[4] = a1.x; v[5] = a1.y; v[6] = a1.z; v[7] = a1.w;
            pn = g_pernode[r];
        } else {
            #pragma unroll
            for (int a = 0; a < 8; a++) v[a] = 16;   // sentinel group
        }
        #pragma unroll
        for (int a = 0; a < 8; a++) {
            unsigned mask   = __match_any_sync(0xffffffffu, v[a]);
            unsigned rank   = __popc(mask & ((1u << lane) - 1u));
            int      leader = __ffs(mask) - 1;
            unsigned old    = 0;
            if (lane == leader && v[a] < 16) {
                int bin = a * 16 + v[a];
                old = soff[bin];
                soff[bin] = old + __popc(mask);
            }
            old = __shfl_sync(0xffffffffu, old, leader);
            if (act) g_sorted[old + rank] = pn;
        }
        __syncwarp();
    }
}

// ---------------- K3: per-bin sequential fp32 left-fold --------------------
// One CTA per bin: warp1 streams data into an smem double buffer, thread 0
// replicates the reference's serial fp32 accumulation.
__global__ void __launch_bounds__(64) k3_fold() {
    __shared__ float4 buf[2][FOLD_BUF / 4];
    int bin = blockIdx.x;
    int tid = threadIdx.x;
    unsigned n    = g_bintotal[bin];
    unsigned base = g_binbase[bin];
    int rounds = (int)((n + FOLD_BUF - 1) / FOLD_BUF);

    // prologue: fill buf[0] (reads may run past n but stay inside g_sorted)
    {
        float* dst = reinterpret_cast<float*>(buf[0]);
        for (int j = tid; j < FOLD_BUF; j += 64) dst[j] = g_sorted[base + j];
    }
    __syncthreads();

    float s = 0.0f;
    for (int r = 0; r < rounds; r++) {
        if (tid >= 32) {                       // filler warp: prefetch round r+1
            if (r + 1 < rounds) {
                int l = tid - 32;
                unsigned o = base + (unsigned)(r + 1) * FOLD_BUF;
                float* dst = reinterpret_cast<float*>(buf[(r + 1) & 1]);
                #pragma unroll
                for (int j = 0; j < FOLD_BUF / 32; j++)
                    dst[j * 32 + l] = g_sorted[o + j * 32 + l];
            }
        } else if (tid == 0) {                 // fold thread: serial fp32 chain
            const float4* b4 = buf[r & 1];
            const float*  bf = reinterpret_cast<const float*>(b4);
            int cnt = min(FOLD_BUF, (int)(n - (unsigned)r * FOLD_BUF));
            int i = 0;
            if (cnt >= 8) {
                float4 c0 = b4[0], c1 = b4[1];
                for (i = 0; i + 16 <= cnt; i += 8) {
                    float4 n0 = b4[i / 4 + 2], n1 = b4[i / 4 + 3];
                    s = __fadd_rn(s, c0.x); s = __fadd_rn(s, c0.y);
                    s = __fadd_rn(s, c0.z); s = __fadd_rn(s, c0.w);
                    s = __fadd_rn(s, c1.x); s = __fadd_rn(s, c1.y);
                    s = __fadd_rn(s, c1.z); s = __fadd_rn(s, c1.w);
                    c0 = n0; c1 = n1;
                }
                s = __fadd_rn(s, c0.x); s = __fadd_rn(s, c0.y);
                s = __fadd_rn(s, c0.z); s = __fadd_rn(s, c0.w);
                s = __fadd_rn(s, c1.x); s = __fadd_rn(s, c1.y);
                s = __fadd_rn(s, c1.z); s = __fadd_rn(s, c1.w);
                i += 8;
            }
            for (; i < cnt; i++) s = __fadd_rn(s, bf[i]);
        }
        __syncthreads();
    }
    if (tid == 0)
        g_binmean[bin] = (n > 0) ? __fdiv_rn(s, (float)n) : 0.0f;
}

// ---------------- K4: pairwise squared diffs (fp32 like reference) ---------
__global__ void __launch_bounds__(128) k4_final(float* __restrict__ out) {
    __shared__ float  m[NBIN];
    __shared__ int    pres[NBIN];
    __shared__ double sl[128];
    __shared__ int    sc[128];
    int t = threadIdx.x;
    m[t]    = g_binmean[t];
    pres[t] = (g_bintotal[t] > 0);
    __syncthreads();
    double loss = 0.0;
    int    ncmp = 0;
    for (int idx = t; idx < 8 * 256; idx += 128) {
        int aa = idx >> 8, i = (idx >> 4) & 15, j = idx & 15;
        if (j > i) {
            int bi = aa * 16 + i, bj = aa * 16 + j;
            if (pres[bi] && pres[bj]) {
                float d  = __fsub_rn(m[bi], m[bj]);
                float dd = __fmul_rn(d, d);
                loss += (double)dd;
                ncmp += 1;
            }
        }
    }
    sl[t] = loss; sc[t] = ncmp;
    __syncthreads();
    for (int o = 64; o > 0; o >>= 1) {
        if (t < o) { sl[t] += sl[t + o]; sc[t] += sc[t + o]; }
        __syncthreads();
    }
    if (t == 0)
        out[0] = (sc[0] > 0) ? (float)(sl[0] / (double)sc[0]) : 0.0f;
}

extern "C" void kernel_launch(void* const* d_in, const int* in_sizes, int n_in,
                              void* d_out, int out_size) {
    const float* pred  = (const float*)d_in[0];
    const int*   attrs = (const int*)d_in[1];
    int B = in_sizes[0] / 8;
    if (B > MAX_B) B = MAX_B;
    int nchunk = (B + CHUNK - 1) / CHUNK;

    k1_pernode<<<(B + 255) / 256, 256>>>(pred, B);
    k2a_count <<<nchunk, 256>>>(attrs, B);
    k2b_scan  <<<1, 128>>>(nchunk);
    k2c_scatter<<<nchunk, 32>>>(attrs, B);
    k3_fold   <<<NBIN, 64>>>();
    k4_final  <<<1, 128>>>((float*)d_out);
}